// round 9
// baseline (speedup 1.0000x reference)
#include <cuda_runtime.h>
#include <math.h>
#include <stddef.h>

#define Bsz 256
#define Dd  512
#define Hh  512
#define Uu  24
#define Kk  8
#define IKk 64
#define IVv 400
#define CKk 32
#define NCHh 4
#define CVv 512

// ---------------- scratch (static device globals; no allocation) ----------------
__device__ float g_k0[Bsz * IKk];
__device__ float g_v0[Bsz * IVv];
__device__ float g_s0[Bsz * Uu];
__device__ float g_p0[Bsz * Uu];
__device__ float g_mask[Bsz * Uu];
__device__ float g_inp[Bsz * Uu * IVv];
__device__ float g_pre[(size_t)Bsz * Uu * 4 * Hh];   // 50 MB
__device__ float g_ht[Bsz * Uu * Hh];
__device__ float g_ct[Bsz * Uu * Hh];
__device__ float g_qc[Bsz * Uu * NCHh * CKk];
__device__ float g_kc[Bsz * Uu * NCHh * CKk];
__device__ float g_vc[(size_t)Bsz * Uu * NCHh * CVv];  // 50 MB
__device__ float g_ctx[(size_t)Bsz * Uu * NCHh * CVv]; // 50 MB

// ---------------- stage A: k0 = x@key_w+key_b, v0 = x@value_w+value_b ----------
__global__ void kv_kernel(const float* __restrict__ x,
                          const float* __restrict__ key_w, const float* __restrict__ key_b,
                          const float* __restrict__ value_w, const float* __restrict__ value_b) {
    int b = blockIdx.x;
    __shared__ float xs[Dd];
    int tid = threadIdx.x; // 512
    xs[tid] = x[(size_t)b * Dd + tid];
    __syncthreads();
    if (tid < IVv) {
        float acc = value_b[tid];
        #pragma unroll 8
        for (int d = 0; d < Dd; d++) acc += xs[d] * value_w[(size_t)d * IVv + tid];
        g_v0[b * IVv + tid] = acc;
    } else if (tid < IVv + IKk) {
        int ik = tid - IVv;
        float acc = key_b[ik];
        #pragma unroll 8
        for (int d = 0; d < Dd; d++) acc += xs[d] * key_w[(size_t)d * IKk + ik];
        g_k0[b * IKk + ik] = acc;
    }
}

// ---------------- stage A: q, scores, probs ----------------
__global__ void qscore_kernel(const float* __restrict__ hs,
                              const float* __restrict__ query_w,
                              const float* __restrict__ key_b) {
    int bu = blockIdx.x;
    int b = bu / Uu, u = bu % Uu;
    int ik = threadIdx.x; // 64
    __shared__ float hss[Hh];
    for (int i = ik; i < Hh; i += 64) hss[i] = hs[(size_t)bu * Hh + i];
    __syncthreads();
    const float* qw = query_w + (size_t)u * Hh * IKk;
    float q = 0.f;
    #pragma unroll 8
    for (int d = 0; d < Hh; d++) q += hss[d] * qw[(size_t)d * IKk + ik];
    float p0 = q * g_k0[b * IKk + ik];
    float p1 = q * key_b[ik];
    #pragma unroll
    for (int off = 16; off > 0; off >>= 1) {
        p0 += __shfl_down_sync(0xffffffffu, p0, off);
        p1 += __shfl_down_sync(0xffffffffu, p1, off);
    }
    __shared__ float r0[2], r1[2];
    if ((ik & 31) == 0) { r0[ik >> 5] = p0; r1[ik >> 5] = p1; }
    __syncthreads();
    if (ik == 0) {
        float s0 = (r0[0] + r0[1]) * 0.125f;   // / sqrt(64)
        float s1 = (r1[0] + r1[1]) * 0.125f;
        g_s0[bu] = s0;
        float m = fmaxf(s0, s1);
        float e0 = expf(s0 - m), e1 = expf(s1 - m);
        g_p0[bu] = e0 / (e0 + e1);
    }
}

// ---------------- top-k mask (jax.lax.top_k tie-break: lower index wins) -------
__global__ void topk_kernel() {
    int b = threadIdx.x; // 256 threads, 1 block
    float s[Uu];
    #pragma unroll
    for (int u = 0; u < Uu; u++) s[u] = g_s0[b * Uu + u];
    #pragma unroll
    for (int u = 0; u < Uu; u++) {
        int cnt = 0;
        #pragma unroll
        for (int t = 0; t < Uu; t++)
            if (s[t] > s[u] || (s[t] == s[u] && t < u)) cnt++;
        g_mask[b * Uu + u] = (cnt < Kk) ? 1.f : 0.f;
    }
}

// ---------------- inp = mask * (p0*v0 + (1-p0)*value_b) ----------------
__global__ void inp_kernel(const float* __restrict__ value_b) {
    int idx = blockIdx.x * blockDim.x + threadIdx.x;
    if (idx >= Bsz * Uu * IVv) return;
    int iv = idx % IVv;
    int bu = idx / IVv;
    int b = bu / Uu;
    float p0 = g_p0[bu];
    float v = p0 * g_v0[b * IVv + iv] + (1.f - p0) * value_b[iv];
    g_inp[idx] = g_mask[bu] * v;
}

// ===================== 128x128x16 double-buffered SGEMM =====================
// C[(b*U+u)*N + n] = sum_k A1[u*a1_uoff + b*a1_rs + k] * W1[u*K1*N + k*N + n]
//                  (+ same for A2/W2 if K2>0, mode != 2)
// mode 0: store into C.
// mode 1 (co epilogue, N==Hh): out = mask ? acc+ht : hs_in
// mode 2 (qk dual): grid.x selects (W1 -> C) vs (W2 -> C2), N == 128, single pass.
#define BM 128
#define BN 128
#define BKt 16

__global__ void __launch_bounds__(256) sgemm128(
    const float* __restrict__ A1, int a1_uoff, int a1_rs, const float* __restrict__ W1, int K1,
    const float* __restrict__ A2, int a2_uoff, int a2_rs, const float* __restrict__ W2, int K2,
    int N, float* __restrict__ C, int mode,
    float* __restrict__ C2,
    const float* __restrict__ ht, const float* __restrict__ mk,
    const float* __restrict__ hs_in, float* __restrict__ outp)
{
    __shared__ __align__(16) float As[2][BKt][BM];
    __shared__ __align__(16) float Ws[2][BKt][BN];

    int u  = blockIdx.z;
    int m0 = blockIdx.y * BM;
    int n0;
    const float* W1sel = W1;
    float* Csel = C;
    if (mode == 2) {
        n0 = 0;
        if (blockIdx.x) { W1sel = W2; Csel = C2; }
    } else {
        n0 = blockIdx.x * BN;
    }

    int tid = threadIdx.x;
    // A tile loading: 128 rows x 16 k; each thread: 2 float4
    int arow = tid >> 2;           // 0..63
    int acol = (tid & 3) * 4;      // 0,4,8,12
    // W tile loading: 16 k x 128 n; each thread: 2 float4
    int wrow = tid >> 5;           // 0..7
    int wcol = (tid & 31) * 4;     // 0..124
    // compute mapping: 16x16 threads, 8x8 micro-tile split as 4+4 with +64 offset
    int tx = (tid & 15) * 4;
    int ty = (tid >> 4) * 4;

    float acc[8][8];
    #pragma unroll
    for (int i = 0; i < 8; i++)
        #pragma unroll
        for (int j = 0; j < 8; j++) acc[i][j] = 0.f;

    #pragma unroll 1
    for (int pass = 0; pass < 2; pass++) {
        const float* A; const float* W; int K, uoff, ars;
        if (pass == 0) { A = A1; W = W1sel; K = K1; uoff = a1_uoff; ars = a1_rs; }
        else {
            if (mode == 2 || K2 == 0) break;
            A = A2; W = W2; K = K2; uoff = a2_uoff; ars = a2_rs;
        }
        const float* Au = A + (size_t)u * uoff;
        const float* Wu = W + (size_t)u * K * N;
        int T = K / BKt;

        float4 ra0, ra1, rw0, rw1;
        // prefetch tile 0
        ra0 = *(const float4*)&Au[(size_t)(m0 + arow) * ars + acol];
        ra1 = *(const float4*)&Au[(size_t)(m0 + arow + 64) * ars + acol];
        rw0 = *(const float4*)&Wu[(size_t)wrow * N + n0 + wcol];
        rw1 = *(const float4*)&Wu[(size_t)(wrow + 8) * N + n0 + wcol];
        // store into buffer 0
        As[0][acol + 0][arow] = ra0.x;
        As[0][acol + 1][arow] = ra0.y;
        As[0][acol + 2][arow] = ra0.z;
        As[0][acol + 3][arow] = ra0.w;
        As[0][acol + 0][arow + 64] = ra1.x;
        As[0][acol + 1][arow + 64] = ra1.y;
        As[0][acol + 2][arow + 64] = ra1.z;
        As[0][acol + 3][arow + 64] = ra1.w;
        *(float4*)&Ws[0][wrow][wcol]     = rw0;
        *(float4*)&Ws[0][wrow + 8][wcol] = rw1;
        __syncthreads();

        #pragma unroll 1
        for (int t = 0; t < T; t++) {
            int cur = t & 1, nxt = cur ^ 1;
            if (t + 1 < T) {
                int k0 = (t + 1) * BKt;
                ra0 = *(const float4*)&Au[(size_t)(m0 + arow) * ars + k0 + acol];
                ra1 = *(const float4*)&Au[(size_t)(m0 + arow + 64) * ars + k0 + acol];
                rw0 = *(const float4*)&Wu[(size_t)(k0 + wrow) * N + n0 + wcol];
                rw1 = *(const float4*)&Wu[(size_t)(k0 + wrow + 8) * N + n0 + wcol];
            }
            #pragma unroll
            for (int kk = 0; kk < BKt; kk++) {
                float a[8], w[8];
                *(float4*)&a[0] = *(const float4*)&As[cur][kk][ty];
                *(float4*)&a[4] = *(const float4*)&As[cur][kk][ty + 64];
                *(float4*)&w[0] = *(const float4*)&Ws[cur][kk][tx];
                *(float4*)&w[4] = *(const float4*)&Ws[cur][kk][tx + 64];
                #pragma unroll
                for (int i = 0; i < 8; i++)
                    #pragma unroll
                    for (int j = 0; j < 8; j++)
                        acc[i][j] += a[i] * w[j];
            }
            if (t + 1 < T) {
                As[nxt][acol + 0][arow] = ra0.x;
                As[nxt][acol + 1][arow] = ra0.y;
                As[nxt][acol + 2][arow] = ra0.z;
                As[nxt][acol + 3][arow] = ra0.w;
                As[nxt][acol + 0][arow + 64] = ra1.x;
                As[nxt][acol + 1][arow + 64] = ra1.y;
                As[nxt][acol + 2][arow + 64] = ra1.z;
                As[nxt][acol + 3][arow + 64] = ra1.w;
                *(float4*)&Ws[nxt][wrow][wcol]     = rw0;
                *(float4*)&Ws[nxt][wrow + 8][wcol] = rw1;
            }
            __syncthreads();
        }
    }

    // epilogue: rows (ty..ty+3, ty+64..ty+67), cols (tx..tx+3, tx+64..tx+67)
    #pragma unroll
    for (int ih = 0; ih < 2; ih++) {
        #pragma unroll
        for (int i = 0; i < 4; i++) {
            int m = m0 + ty + ih * 64 + i;
            int bu = m * Uu + u;
            size_t rowbase = (size_t)bu * N + n0;
            #pragma unroll
            for (int jh = 0; jh < 2; jh++) {
                int n = tx + jh * 64;
                float4 v;
                v.x = acc[ih * 4 + i][jh * 4 + 0];
                v.y = acc[ih * 4 + i][jh * 4 + 1];
                v.z = acc[ih * 4 + i][jh * 4 + 2];
                v.w = acc[ih * 4 + i][jh * 4 + 3];
                size_t idx = rowbase + n;
                if (mode == 1) {
                    if (mk[bu] != 0.f) {
                        float4 h = *(const float4*)&ht[idx];
                        v.x += h.x; v.y += h.y; v.z += h.z; v.w += h.w;
                    } else {
                        v = *(const float4*)&hs_in[idx];
                    }
                    *(float4*)&outp[idx] = v;
                } else {
                    *(float4*)&Csel[idx] = v;
                }
            }
        }
    }
}

// ---------------- LSTM gates + cs_new output ----------------
__global__ void gates_kernel(const float* __restrict__ cs, float* __restrict__ out_cs) {
    int idx = blockIdx.x * blockDim.x + threadIdx.x;
    if (idx >= Bsz * Uu * Hh) return;
    int h  = idx % Hh;
    int bu = idx / Hh;
    size_t base = (size_t)bu * 4 * Hh;
    float pi = g_pre[base + h];
    float pf = g_pre[base + Hh + h];
    float po = g_pre[base + 2 * Hh + h];
    float pg = g_pre[base + 3 * Hh + h];
    float it = 1.f / (1.f + expf(-pi));
    float ft = 1.f / (1.f + expf(-pf));
    float ot = 1.f / (1.f + expf(-po));
    float gt = tanhf(pg);
    float c  = cs[idx] * ft + it * gt;
    g_ct[idx] = c;
    g_ht[idx] = ot * tanhf(c);
    out_cs[idx] = (g_mask[bu] != 0.f) ? c : cs[idx];
}

// ---------------- communication attention: ctx[b,u,head*512+v] ----------------
__global__ void __launch_bounds__(256) attn_kernel() {
    int b = blockIdx.x >> 2;
    int head = blockIdx.x & 3;
    __shared__ float qcs[Uu][CKk + 1], kcs[Uu][CKk + 1], att[Uu][Uu];
    int tid = threadIdx.x;
    for (int i = tid; i < Uu * CKk; i += 256) {
        int uu = i / CKk, c = i % CKk;
        size_t base = (size_t)(b * Uu + uu) * (NCHh * CKk) + head * CKk + c;
        qcs[uu][c] = g_qc[base];
        kcs[uu][c] = g_kc[base];
    }
    __syncthreads();
    for (int i = tid; i < Uu * Uu; i += 256) {
        int uu = i / Uu, t = i % Uu;
        float s = 0.f;
        #pragma unroll
        for (int c = 0; c < CKk; c++) s += qcs[uu][c] * kcs[t][c];
        att[uu][t] = s * 0.17677669529663687f; // 1/sqrt(32)
    }
    __syncthreads();
    if (tid < Uu) {
        float m = -1e30f;
        #pragma unroll
        for (int t = 0; t < Uu; t++) m = fmaxf(m, att[tid][t]);
        float sum = 0.f;
        #pragma unroll
        for (int t = 0; t < Uu; t++) {
            float e = expf(att[tid][t] - m);
            att[tid][t] = e;
            sum += e;
        }
        float inv = 1.f / sum;
        #pragma unroll
        for (int t = 0; t < Uu; t++) att[tid][t] *= inv;
    }
    __syncthreads();
    float accx[Uu], accy[Uu];
    #pragma unroll
    for (int uu = 0; uu < Uu; uu++) { accx[uu] = 0.f; accy[uu] = 0.f; }
    int v0 = tid * 2;
    #pragma unroll 4
    for (int t = 0; t < Uu; t++) {
        float2 vv = *(const float2*)&g_vc[(size_t)(b * Uu + t) * (NCHh * CVv) + head * CVv + v0];
        #pragma unroll
        for (int uu = 0; uu < Uu; uu++) {
            float a = att[uu][t];
            accx[uu] += a * vv.x;
            accy[uu] += a * vv.y;
        }
    }
    #pragma unroll
    for (int uu = 0; uu < Uu; uu++) {
        float2 o; o.x = accx[uu]; o.y = accy[uu];
        *(float2*)&g_ctx[(size_t)(b * Uu + uu) * (NCHh * CVv) + head * CVv + v0] = o;
    }
}

// ---------------- launch ----------------
extern "C" void kernel_launch(void* const* d_in, const int* in_sizes, int n_in,
                              void* d_out, int out_size) {
    const float* x       = (const float*)d_in[0];
    const float* hs      = (const float*)d_in[1];
    const float* cs      = (const float*)d_in[2];
    const float* key_w   = (const float*)d_in[3];
    const float* key_b   = (const float*)d_in[4];
    const float* value_w = (const float*)d_in[5];
    const float* value_b = (const float*)d_in[6];
    const float* query_w = (const float*)d_in[7];
    const float* i2h_w   = (const float*)d_in[8];
    const float* h2h_w   = (const float*)d_in[9];
    const float* qc_w    = (const float*)d_in[10];
    const float* kc_w    = (const float*)d_in[11];
    const float* vc_w    = (const float*)d_in[12];
    const float* co_w    = (const float*)d_in[13];
    float* out    = (float*)d_out;
    float* out_hs = out;
    float* out_cs = out + (size_t)Bsz * Uu * Hh;

    float *p_inp, *p_pre, *p_ht, *p_qc, *p_kc, *p_vc, *p_ctx, *p_mask;
    cudaGetSymbolAddress((void**)&p_inp,  g_inp);
    cudaGetSymbolAddress((void**)&p_pre,  g_pre);
    cudaGetSymbolAddress((void**)&p_ht,   g_ht);
    cudaGetSymbolAddress((void**)&p_qc,   g_qc);
    cudaGetSymbolAddress((void**)&p_kc,   g_kc);
    cudaGetSymbolAddress((void**)&p_vc,   g_vc);
    cudaGetSymbolAddress((void**)&p_ctx,  g_ctx);
    cudaGetSymbolAddress((void**)&p_mask, g_mask);

    kv_kernel<<<Bsz, 512>>>(x, key_w, key_b, value_w, value_b);
    qscore_kernel<<<Bsz * Uu, 64>>>(hs, query_w, key_b);
    topk_kernel<<<1, Bsz>>>();
    inp_kernel<<<(Bsz * Uu * IVv + 255) / 256, 256>>>(value_b);

    // preact = inp @ i2h_w[u] + hs @ h2h_w[u]   (M=256, N=2048, K=400+512, per u)
    {
        dim3 g(4 * Hh / BN, Bsz / BM, Uu);
        sgemm128<<<g, 256>>>(p_inp, IVv, Uu * IVv, i2h_w, IVv,
                             hs,    Hh,  Uu * Hh,  h2h_w, Hh,
                             4 * Hh, p_pre, 0, nullptr,
                             nullptr, nullptr, nullptr, nullptr);
    }
    gates_kernel<<<(Bsz * Uu * Hh + 255) / 256, 256>>>(cs, out_cs);

    // qc & kc merged: one launch, grid.x selects weight/output (N=128 each)
    {
        dim3 g(2, Bsz / BM, Uu);
        sgemm128<<<g, 256>>>(p_ht, Hh, Uu * Hh, qc_w, Hh,
                             nullptr, 0, 0, kc_w, 0,
                             128, p_qc, 2, p_kc,
                             nullptr, nullptr, nullptr, nullptr);
    }
    // vc (N=2048) from h_t
    {
        dim3 g(NCHh * CVv / BN, Bsz / BM, Uu);
        sgemm128<<<g, 256>>>(p_ht, Hh, Uu * Hh, vc_w, Hh,
                             nullptr, 0, 0, nullptr, 0,
                             NCHh * CVv, p_vc, 0, nullptr,
                             nullptr, nullptr, nullptr, nullptr);
    }

    attn_kernel<<<Bsz * NCHh, 256>>>();

    // ctxo = ctx @ co_w[u]; hs_new = mask ? ctxo + h_t : hs   (fused epilogue)
    {
        dim3 g(Hh / BN, Bsz / BM, Uu);
        sgemm128<<<g, 256>>>(p_ctx, NCHh * CVv, Uu * NCHh * CVv, co_w, NCHh * CVv,
                             nullptr, 0, 0, nullptr, 0,
                             Hh, nullptr, 1, nullptr,
                             p_ht, p_mask, hs, out_hs);
    }
}

// round 11
// speedup vs baseline: 2.0743x; 2.0743x over previous
#include <cuda_runtime.h>
#include <cuda_bf16.h>
#include <math.h>
#include <stddef.h>
#include <stdint.h>

#define Bsz 256
#define Dd  512
#define Hh  512
#define Uu  24
#define Kk  8
#define IKk 64
#define IVv 400
#define IVP 416        // IVv padded to multiple of 32
#define CKk 32
#define NCHh 4
#define CVv 512

typedef __nv_bfloat16 bf16;

// ---------------- fp32 scratch ----------------
__device__ float g_k0[Bsz * IKk];
__device__ float g_v0[Bsz * IVv];
__device__ float g_s0[Bsz * Uu];
__device__ float g_p0[Bsz * Uu];
__device__ float g_mask[Bsz * Uu];
__device__ float g_pre[(size_t)Bsz * Uu * 4 * Hh];   // 50 MB
__device__ float g_ht[Bsz * Uu * Hh];
__device__ float g_qc[Bsz * Uu * NCHh * CKk];
__device__ float g_kc[Bsz * Uu * NCHh * CKk];
__device__ float g_vc[(size_t)Bsz * Uu * NCHh * CVv];  // 50 MB

// ---------------- bf16 hi/lo activations (A operands) -------------
__device__ __align__(16) bf16 g_inp_h[Bsz * Uu * IVP];
__device__ __align__(16) bf16 g_inp_l[Bsz * Uu * IVP];
__device__ __align__(16) bf16 g_hs_h[Bsz * Uu * Hh];
__device__ __align__(16) bf16 g_hs_l[Bsz * Uu * Hh];
__device__ __align__(16) bf16 g_hth[Bsz * Uu * Hh];
__device__ __align__(16) bf16 g_htl[Bsz * Uu * Hh];
__device__ __align__(16) bf16 g_ctx_h[(size_t)Bsz * Uu * NCHh * CVv];
__device__ __align__(16) bf16 g_ctx_l[(size_t)Bsz * Uu * NCHh * CVv];

// ---------------- bf16 hi/lo transposed weights [u][N][Kp] ---------
#define I2H_SZ ((size_t)24 * 2048 * IVP)
#define H2H_SZ ((size_t)24 * 2048 * 512)
#define QCW_SZ ((size_t)24 * 128 * 512)
#define VCW_SZ ((size_t)24 * 2048 * 512)
#define COW_SZ ((size_t)24 * 512 * 2048)
__device__ __align__(16) bf16 g_i2h_h[I2H_SZ]; __device__ __align__(16) bf16 g_i2h_l[I2H_SZ];
__device__ __align__(16) bf16 g_h2h_h[H2H_SZ]; __device__ __align__(16) bf16 g_h2h_l[H2H_SZ];
__device__ __align__(16) bf16 g_qcw_h[QCW_SZ]; __device__ __align__(16) bf16 g_qcw_l[QCW_SZ];
__device__ __align__(16) bf16 g_kcw_h[QCW_SZ]; __device__ __align__(16) bf16 g_kcw_l[QCW_SZ];
__device__ __align__(16) bf16 g_vcw_h[VCW_SZ]; __device__ __align__(16) bf16 g_vcw_l[VCW_SZ];
__device__ __align__(16) bf16 g_cow_h[COW_SZ]; __device__ __align__(16) bf16 g_cow_l[COW_SZ];

// ===================== PTX helpers (baseline sm_80+ only) =====================
__device__ __forceinline__ uint32_t smem_u32(const void* p) {
    uint32_t a;
    asm("{ .reg .u64 t; cvta.to.shared.u64 t, %1; cvt.u32.u64 %0, t; }" : "=r"(a) : "l"(p));
    return a;
}
__device__ __forceinline__ void cp16(uint32_t dst, const void* src) {
    asm volatile("cp.async.cg.shared.global [%0], [%1], 16;"
                 :: "r"(dst), "l"(__cvta_generic_to_global(src)) : "memory");
}
__device__ __forceinline__ void cp_commit() {
    asm volatile("cp.async.commit_group;" ::: "memory");
}
__device__ __forceinline__ void cp_wait0() {
    asm volatile("cp.async.wait_group 0;" ::: "memory");
}
__device__ __forceinline__ void cp_wait1() {
    asm volatile("cp.async.wait_group 1;" ::: "memory");
}
__device__ __forceinline__ void ldsm_x4(uint32_t* r, uint32_t addr) {
    asm volatile("ldmatrix.sync.aligned.m8n8.x4.shared.b16 {%0,%1,%2,%3}, [%4];"
                 : "=r"(r[0]), "=r"(r[1]), "=r"(r[2]), "=r"(r[3]) : "r"(addr));
}
__device__ __forceinline__ void ldsm_x2(uint32_t* r, uint32_t addr) {
    asm volatile("ldmatrix.sync.aligned.m8n8.x2.shared.b16 {%0,%1}, [%2];"
                 : "=r"(r[0]), "=r"(r[1]) : "r"(addr));
}
__device__ __forceinline__ void mma_bf16(float* d, const uint32_t* a, const uint32_t* b) {
    asm volatile(
        "mma.sync.aligned.m16n8k16.row.col.f32.bf16.bf16.f32 "
        "{%0,%1,%2,%3}, {%4,%5,%6,%7}, {%8,%9}, {%0,%1,%2,%3};"
        : "+f"(d[0]), "+f"(d[1]), "+f"(d[2]), "+f"(d[3])
        : "r"(a[0]), "r"(a[1]), "r"(a[2]), "r"(a[3]), "r"(b[0]), "r"(b[1]));
}

// ---------------- stage A: k0 = x@key_w+key_b, v0 = x@value_w+value_b ------
__global__ void kv_kernel(const float* __restrict__ x,
                          const float* __restrict__ key_w, const float* __restrict__ key_b,
                          const float* __restrict__ value_w, const float* __restrict__ value_b) {
    int b = blockIdx.x;
    __shared__ float xs[Dd];
    int tid = threadIdx.x; // 512
    xs[tid] = x[(size_t)b * Dd + tid];
    __syncthreads();
    if (tid < IVv) {
        float acc = value_b[tid];
        #pragma unroll 8
        for (int d = 0; d < Dd; d++) acc += xs[d] * value_w[(size_t)d * IVv + tid];
        g_v0[b * IVv + tid] = acc;
    } else if (tid < IVv + IKk) {
        int ik = tid - IVv;
        float acc = key_b[ik];
        #pragma unroll 8
        for (int d = 0; d < Dd; d++) acc += xs[d] * key_w[(size_t)d * IKk + ik];
        g_k0[b * IKk + ik] = acc;
    }
}

// ---------------- stage A: q, scores, probs ----------------
__global__ void qscore_kernel(const float* __restrict__ hs,
                              const float* __restrict__ query_w,
                              const float* __restrict__ key_b) {
    int bu = blockIdx.x;
    int b = bu / Uu, u = bu % Uu;
    int ik = threadIdx.x; // 64
    __shared__ float hss[Hh];
    for (int i = ik; i < Hh; i += 64) hss[i] = hs[(size_t)bu * Hh + i];
    __syncthreads();
    const float* qw = query_w + (size_t)u * Hh * IKk;
    float q = 0.f;
    #pragma unroll 8
    for (int d = 0; d < Hh; d++) q += hss[d] * qw[(size_t)d * IKk + ik];
    float p0 = q * g_k0[b * IKk + ik];
    float p1 = q * key_b[ik];
    #pragma unroll
    for (int off = 16; off > 0; off >>= 1) {
        p0 += __shfl_down_sync(0xffffffffu, p0, off);
        p1 += __shfl_down_sync(0xffffffffu, p1, off);
    }
    __shared__ float r0[2], r1[2];
    if ((ik & 31) == 0) { r0[ik >> 5] = p0; r1[ik >> 5] = p1; }
    __syncthreads();
    if (ik == 0) {
        float s0 = (r0[0] + r0[1]) * 0.125f;
        float s1 = (r1[0] + r1[1]) * 0.125f;
        g_s0[bu] = s0;
        float m = fmaxf(s0, s1);
        float e0 = expf(s0 - m), e1 = expf(s1 - m);
        g_p0[bu] = e0 / (e0 + e1);
    }
}

// ---------------- top-k mask ----------------
__global__ void topk_kernel() {
    int b = threadIdx.x;
    float s[Uu];
    #pragma unroll
    for (int u = 0; u < Uu; u++) s[u] = g_s0[b * Uu + u];
    #pragma unroll
    for (int u = 0; u < Uu; u++) {
        int cnt = 0;
        #pragma unroll
        for (int t = 0; t < Uu; t++)
            if (s[t] > s[u] || (s[t] == s[u] && t < u)) cnt++;
        g_mask[b * Uu + u] = (cnt < Kk) ? 1.f : 0.f;
    }
}

// ---------------- inp (bf16 hi/lo out, padded K to 416) ----------------
__global__ void inp_kernel(const float* __restrict__ value_b) {
    int idx = blockIdx.x * blockDim.x + threadIdx.x;
    if (idx >= Bsz * Uu * IVP) return;
    int iv = idx % IVP;
    int bu = idx / IVP;
    int b = bu / Uu;
    float v = 0.f;
    if (iv < IVv) {
        float p0 = g_p0[bu];
        v = p0 * g_v0[b * IVv + iv] + (1.f - p0) * value_b[iv];
        v *= g_mask[bu];
    }
    bf16 h = __float2bfloat16_rn(v);
    g_inp_h[idx] = h;
    g_inp_l[idx] = __float2bfloat16_rn(v - __bfloat162float(h));
}

// ---------------- hs -> bf16 hi/lo ----------------
__global__ void hsconv_kernel(const float* __restrict__ hs) {
    int idx = blockIdx.x * blockDim.x + threadIdx.x;
    if (idx >= Bsz * Uu * Hh) return;
    float v = hs[idx];
    bf16 h = __float2bfloat16_rn(v);
    g_hs_h[idx] = h;
    g_hs_l[idx] = __float2bfloat16_rn(v - __bfloat162float(h));
}

// ---------------- weight transpose+split: W[u][K][N] f32 -> T[u][N][Kp] bf16 ----
__global__ void wconv_kernel(const float* __restrict__ W, bf16* __restrict__ Th,
                             bf16* __restrict__ Tl, int K, int Kp, int N) {
    __shared__ float t[32][33];
    int u = blockIdx.z;
    int n0 = blockIdx.x * 32, k0 = blockIdx.y * 32;
    int tx = threadIdx.x, ty = threadIdx.y; // (32,8)
    const float* Wu = W + (size_t)u * K * N;
    #pragma unroll
    for (int i = 0; i < 4; i++) {
        int k = k0 + ty + 8 * i;
        if (k < K) t[ty + 8 * i][tx] = Wu[(size_t)k * N + n0 + tx];
    }
    __syncthreads();
    bf16* Thu = Th + (size_t)u * N * Kp;
    bf16* Tlu = Tl + (size_t)u * N * Kp;
    int k = k0 + tx;
    if (k < Kp) {
        #pragma unroll
        for (int i = 0; i < 4; i++) {
            int n = n0 + ty + 8 * i;
            float v = (k < K) ? t[tx][ty + 8 * i] : 0.f;
            bf16 h = __float2bfloat16_rn(v);
            Thu[(size_t)n * Kp + k] = h;
            Tlu[(size_t)n * Kp + k] = __float2bfloat16_rn(v - __bfloat162float(h));
        }
    }
}

// ===================== bf16-split tensor-core GEMM (mma.sync) =====================
// D[(b*U+u)*ldc + n] = sum_k A(b,u,k) * Bt[u][n][k], hi/lo split, fp32 acc.
// CTA tile 128x128, 8 warps (2 M x 4 N), warp tile 64x32, BK=32, cp.async 2-stage.
// mode 0: store C. mode 1: out = mask ? acc+ht : hs_in. mode 2: blockIdx.x picks
//         (Bh1,C) vs (Bh2,C2), n0=0, single pass.
#define BKc   32
#define BKp   40
#define ATILE (128 * BKp * 2)     // 10240 bytes per tile
#define BUFB  (4 * ATILE)         // Ah, Al, Bh, Bl

extern __shared__ char gsm[];

struct GArgs {
    const bf16 *Auh, *Aul, *Buh, *Bul;
    int K, ars;
};

__device__ __forceinline__ void issue_loads(const GArgs& ga, uint32_t sbuf,
                                            int k0, int tid) {
    #pragma unroll
    for (int h = 0; h < 2; h++) {
        int c = tid + h * 256;
        int row = c >> 2, seg = c & 3;
        uint32_t d = sbuf + (uint32_t)(row * (BKp * 2) + seg * 16);
        const bf16* a_h = ga.Auh + (size_t)row * ga.ars + k0 + seg * 8;
        const bf16* a_l = ga.Aul + (size_t)row * ga.ars + k0 + seg * 8;
        const bf16* b_h = ga.Buh + (size_t)row * ga.K + k0 + seg * 8;
        const bf16* b_l = ga.Bul + (size_t)row * ga.K + k0 + seg * 8;
        cp16(d,             a_h);
        cp16(d + ATILE,     a_l);
        cp16(d + 2 * ATILE, b_h);
        cp16(d + 3 * ATILE, b_l);
    }
    cp_commit();
}

__global__ void __launch_bounds__(256) bgemm(
    const bf16* __restrict__ Ah1, const bf16* __restrict__ Al1, int a1_uoff, int a1_rs,
    const bf16* __restrict__ Bh1, const bf16* __restrict__ Bl1, int K1,
    const bf16* __restrict__ Ah2, const bf16* __restrict__ Al2, int a2_uoff, int a2_rs,
    const bf16* __restrict__ Bh2, const bf16* __restrict__ Bl2, int K2,
    int ldc, float* __restrict__ C, int mode, float* __restrict__ C2,
    const float* __restrict__ ht, const float* __restrict__ mk,
    const float* __restrict__ hs_in, float* __restrict__ outp)
{
    uint32_t sb = smem_u32(gsm);
    int tid  = threadIdx.x;
    int lane = tid & 31, wid = tid >> 5;
    int wm = wid & 1, wn = wid >> 1;
    int u = blockIdx.z, m0 = blockIdx.y * 128;
    int n0;
    const bf16 *Bh = Bh1, *Bl = Bl1;
    float* Csel = C;
    if (mode == 2) {
        n0 = 0;
        if (blockIdx.x) { Bh = Bh2; Bl = Bl2; Csel = C2; }
    } else {
        n0 = blockIdx.x * 128;
    }

    float acc[4][4][4];
    #pragma unroll
    for (int i = 0; i < 4; i++)
        #pragma unroll
        for (int j = 0; j < 4; j++)
            #pragma unroll
            for (int k = 0; k < 4; k++) acc[i][j][k] = 0.f;

    // lane-dependent ldmatrix offsets (bytes)
    int a_ro = lane & 15, a_cg = lane >> 4;
    int b_ro = lane & 7,  b_cg = (lane >> 3) & 1;

    int npass = (mode != 2 && K2 > 0) ? 2 : 1;
    #pragma unroll 1
    for (int pass = 0; pass < npass; pass++) {
        GArgs ga;
        if (pass == 0) {
            ga.Auh = Ah1 + (size_t)u * a1_uoff + (size_t)m0 * a1_rs;
            ga.Aul = Al1 + (size_t)u * a1_uoff + (size_t)m0 * a1_rs;
            ga.Buh = Bh + ((size_t)u * ldc + n0) * K1;
            ga.Bul = Bl + ((size_t)u * ldc + n0) * K1;
            ga.K = K1; ga.ars = a1_rs;
        } else {
            ga.Auh = Ah2 + (size_t)u * a2_uoff + (size_t)m0 * a2_rs;
            ga.Aul = Al2 + (size_t)u * a2_uoff + (size_t)m0 * a2_rs;
            ga.Buh = Bh2 + ((size_t)u * ldc + n0) * K2;
            ga.Bul = Bl2 + ((size_t)u * ldc + n0) * K2;
            ga.K = K2; ga.ars = a2_rs;
        }
        int T = ga.K / BKc;

        issue_loads(ga, sb, 0, tid);

        #pragma unroll 1
        for (int t = 0; t < T; t++) {
            uint32_t scur = sb + (uint32_t)((t & 1) * BUFB);
            if (t + 1 < T) {
                issue_loads(ga, sb + (uint32_t)(((t + 1) & 1) * BUFB), (t + 1) * BKc, tid);
                cp_wait1();
            } else {
                cp_wait0();
            }
            __syncthreads();

            #pragma unroll
            for (int ks = 0; ks < 2; ks++) {
                int koff = ks * 16;
                uint32_t a_h[4][4], a_l[4][4], b_h[4][2], b_l[4][2];
                #pragma unroll
                for (int mt = 0; mt < 4; mt++) {
                    uint32_t ad = scur +
                        (uint32_t)(((wm * 64 + mt * 16 + a_ro) * BKp + koff + a_cg * 8) * 2);
                    ldsm_x4(a_h[mt], ad);
                    ldsm_x4(a_l[mt], ad + ATILE);
                }
                #pragma unroll
                for (int nt = 0; nt < 4; nt++) {
                    uint32_t bd = scur + 2 * ATILE +
                        (uint32_t)(((wn * 32 + nt * 8 + b_ro) * BKp + koff + b_cg * 8) * 2);
                    ldsm_x2(b_h[nt], bd);
                    ldsm_x2(b_l[nt], bd + ATILE);
                }
                // split-major ordering: consecutive MMAs hit independent accumulators
                #pragma unroll
                for (int mt = 0; mt < 4; mt++)
                    #pragma unroll
                    for (int nt = 0; nt < 4; nt++)
                        mma_bf16(acc[mt][nt], a_h[mt], b_h[nt]);
                #pragma unroll
                for (int mt = 0; mt < 4; mt++)
                    #pragma unroll
                    for (int nt = 0; nt < 4; nt++)
                        mma_bf16(acc[mt][nt], a_h[mt], b_l[nt]);
                #pragma unroll
                for (int mt = 0; mt < 4; mt++)
                    #pragma unroll
                    for (int nt = 0; nt < 4; nt++)
                        mma_bf16(acc[mt][nt], a_l[mt], b_h[nt]);
            }
            __syncthreads();
        }
    }

    // epilogue: D fragment layout m16n8 -> rows lane>>2 (+8), cols (lane&3)*2
    #pragma unroll
    for (int mt = 0; mt < 4; mt++) {
        #pragma unroll
        for (int half = 0; half < 2; half++) {
            int row = m0 + wm * 64 + mt * 16 + (lane >> 2) + 8 * half;
            int bu = row * Uu + u;
            bool sel = (mode == 1) ? (mk[bu] != 0.f) : false;
            #pragma unroll
            for (int nt = 0; nt < 4; nt++) {
                int col = n0 + wn * 32 + nt * 8 + (lane & 3) * 2;
                size_t idx = (size_t)bu * ldc + col;
                float2 v;
                v.x = acc[mt][nt][2 * half + 0];
                v.y = acc[mt][nt][2 * half + 1];
                if (mode == 1) {
                    if (sel) {
                        float2 h = *(const float2*)&ht[idx];
                        v.x += h.x; v.y += h.y;
                    } else {
                        v = *(const float2*)&hs_in[idx];
                    }
                    *(float2*)&outp[idx] = v;
                } else {
                    *(float2*)&Csel[idx] = v;
                }
            }
        }
    }
}

// ---------------- LSTM gates + cs_new + ht (f32 + bf16 hi/lo) ----------------
__global__ void gates_kernel(const float* __restrict__ cs, float* __restrict__ out_cs) {
    int idx = blockIdx.x * blockDim.x + threadIdx.x;
    if (idx >= Bsz * Uu * Hh) return;
    int h  = idx % Hh;
    int bu = idx / Hh;
    size_t base = (size_t)bu * 4 * Hh;
    float pi = g_pre[base + h];
    float pf = g_pre[base + Hh + h];
    float po = g_pre[base + 2 * Hh + h];
    float pg = g_pre[base + 3 * Hh + h];
    float it = 1.f / (1.f + expf(-pi));
    float ft = 1.f / (1.f + expf(-pf));
    float ot = 1.f / (1.f + expf(-po));
    float gt = tanhf(pg);
    float c  = cs[idx] * ft + it * gt;
    float htv = ot * tanhf(c);
    g_ht[idx] = htv;
    bf16 hh = __float2bfloat16_rn(htv);
    g_hth[idx] = hh;
    g_htl[idx] = __float2bfloat16_rn(htv - __bfloat162float(hh));
    out_cs[idx] = (g_mask[bu] != 0.f) ? c : cs[idx];
}

// ---------------- communication attention: ctx (bf16 hi/lo out) --------------
__global__ void __launch_bounds__(256) attn_kernel() {
    int b = blockIdx.x >> 2;
    int head = blockIdx.x & 3;
    __shared__ float qcs[Uu][CKk + 1], kcs[Uu][CKk + 1], att[Uu][Uu];
    int tid = threadIdx.x;
    for (int i = tid; i < Uu * CKk; i += 256) {
        int uu = i / CKk, c = i % CKk;
        size_t base = (size_t)(b * Uu + uu) * (NCHh * CKk) + head * CKk + c;
        qcs[uu][c] = g_qc[base];
        kcs[uu][c] = g_kc[base];
    }
    __syncthreads();
    for (int i = tid; i < Uu * Uu; i += 256) {
        int uu = i / Uu, t = i % Uu;
        float s = 0.f;
        #pragma unroll
        for (int c = 0; c < CKk; c++) s += qcs[uu][c] * kcs[t][c];
        att[uu][t] = s * 0.17677669529663687f;
    }
    __syncthreads();
    if (tid < Uu) {
        float m = -1e30f;
        #pragma unroll
        for (int t = 0; t < Uu; t++) m = fmaxf(m, att[tid][t]);
        float sum = 0.f;
        #pragma unroll
        for (int t = 0; t < Uu; t++) {
            float e = expf(att[tid][t] - m);
            att[tid][t] = e;
            sum += e;
        }
        float inv = 1.f / sum;
        #pragma unroll
        for (int t = 0; t < Uu; t++) att[tid][t] *= inv;
    }
    __syncthreads();
    float accx[Uu], accy[Uu];
    #pragma unroll
    for (int uu = 0; uu < Uu; uu++) { accx[uu] = 0.f; accy[uu] = 0.f; }
    int v0 = tid * 2;
    #pragma unroll 4
    for (int t = 0; t < Uu; t++) {
        float2 vv = *(const float2*)&g_vc[(size_t)(b * Uu + t) * (NCHh * CVv) + head * CVv + v0];
        #pragma unroll
        for (int uu = 0; uu < Uu; uu++) {
            float a = att[uu][t];
            accx[uu] += a * vv.x;
            accy[uu] += a * vv.y;
        }
    }
    #pragma unroll
    for (int uu = 0; uu < Uu; uu++) {
        size_t o = (size_t)(b * Uu + uu) * (NCHh * CVv) + head * CVv + v0;
        bf16 hx = __float2bfloat16_rn(accx[uu]);
        bf16 hy = __float2bfloat16_rn(accy[uu]);
        g_ctx_h[o]     = hx;
        g_ctx_h[o + 1] = hy;
        g_ctx_l[o]     = __float2bfloat16_rn(accx[uu] - __bfloat162float(hx));
        g_ctx_l[o + 1] = __float2bfloat16_rn(accy[uu] - __bfloat162float(hy));
    }
}

// ---------------- launch ----------------
extern "C" void kernel_launch(void* const* d_in, const int* in_sizes, int n_in,
                              void* d_out, int out_size) {
    const float* x       = (const float*)d_in[0];
    const float* hs      = (const float*)d_in[1];
    const float* cs      = (const float*)d_in[2];
    const float* key_w   = (const float*)d_in[3];
    const float* key_b   = (const float*)d_in[4];
    const float* value_w = (const float*)d_in[5];
    const float* value_b = (const float*)d_in[6];
    const float* query_w = (const float*)d_in[7];
    const float* i2h_w   = (const float*)d_in[8];
    const float* h2h_w   = (const float*)d_in[9];
    const float* qc_w    = (const float*)d_in[10];
    const float* kc_w    = (const float*)d_in[11];
    const float* vc_w    = (const float*)d_in[12];
    const float* co_w    = (const float*)d_in[13];
    float* out    = (float*)d_out;
    float* out_hs = out;
    float* out_cs = out + (size_t)Bsz * Uu * Hh;

    static const int SMEM_TOTAL = 2 * BUFB; // 81920 bytes
    cudaFuncSetAttribute(bgemm, cudaFuncAttributeMaxDynamicSharedMemorySize, SMEM_TOTAL);

    float *p_pre, *p_ht, *p_qc, *p_kc, *p_vc, *p_mask;
    cudaGetSymbolAddress((void**)&p_pre,  g_pre);
    cudaGetSymbolAddress((void**)&p_ht,   g_ht);
    cudaGetSymbolAddress((void**)&p_qc,   g_qc);
    cudaGetSymbolAddress((void**)&p_kc,   g_kc);
    cudaGetSymbolAddress((void**)&p_vc,   g_vc);
    cudaGetSymbolAddress((void**)&p_mask, g_mask);
    bf16 *p_inp_h, *p_inp_l, *p_hs_h, *p_hs_l, *p_hth, *p_htl, *p_ctx_h, *p_ctx_l;
    cudaGetSymbolAddress((void**)&p_inp_h, g_inp_h);
    cudaGetSymbolAddress((void**)&p_inp_l, g_inp_l);
    cudaGetSymbolAddress((void**)&p_hs_h,  g_hs_h);
    cudaGetSymbolAddress((void**)&p_hs_l,  g_hs_l);
    cudaGetSymbolAddress((void**)&p_hth,   g_hth);
    cudaGetSymbolAddress((void**)&p_htl,   g_htl);
    cudaGetSymbolAddress((void**)&p_ctx_h, g_ctx_h);
    cudaGetSymbolAddress((void**)&p_ctx_l, g_ctx_l);
    bf16 *w_i2h_h, *w_i2h_l, *w_h2h_h, *w_h2h_l, *w_qc_h, *w_qc_l,
         *w_kc_h, *w_kc_l, *w_vc_h, *w_vc_l, *w_co_h, *w_co_l;
    cudaGetSymbolAddress((void**)&w_i2h_h, g_i2h_h);
    cudaGetSymbolAddress((void**)&w_i2h_l, g_i2h_l);
    cudaGetSymbolAddress((void**)&w_h2h_h, g_h2h_h);
    cudaGetSymbolAddress((void**)&w_h2h_l, g_h2h_l);
    cudaGetSymbolAddress((void**)&w_qc_h,  g_qcw_h);
    cudaGetSymbolAddress((void**)&w_qc_l,  g_qcw_l);
    cudaGetSymbolAddress((void**)&w_kc_h,  g_kcw_h);
    cudaGetSymbolAddress((void**)&w_kc_l,  g_kcw_l);
    cudaGetSymbolAddress((void**)&w_vc_h,  g_vcw_h);
    cudaGetSymbolAddress((void**)&w_vc_l,  g_vcw_l);
    cudaGetSymbolAddress((void**)&w_co_h,  g_cow_h);
    cudaGetSymbolAddress((void**)&w_co_l,  g_cow_l);

    // --- weight transpose + bf16 split (Kp padded for i2h) ---
    dim3 tb(32, 8);
    wconv_kernel<<<dim3(2048 / 32, IVP / 32, Uu), tb>>>(i2h_w, w_i2h_h, w_i2h_l, IVv, IVP, 2048);
    wconv_kernel<<<dim3(2048 / 32, 512 / 32, Uu), tb>>>(h2h_w, w_h2h_h, w_h2h_l, 512, 512, 2048);
    wconv_kernel<<<dim3(128 / 32, 512 / 32, Uu), tb>>>(qc_w, w_qc_h, w_qc_l, 512, 512, 128);
    wconv_kernel<<<dim3(128 / 32, 512 / 32, Uu), tb>>>(kc_w, w_kc_h, w_kc_l, 512, 512, 128);
    wconv_kernel<<<dim3(2048 / 32, 512 / 32, Uu), tb>>>(vc_w, w_vc_h, w_vc_l, 512, 512, 2048);
    wconv_kernel<<<dim3(512 / 32, 2048 / 32, Uu), tb>>>(co_w, w_co_h, w_co_l, 2048, 2048, 512);

    // --- stage A ---
    kv_kernel<<<Bsz, 512>>>(x, key_w, key_b, value_w, value_b);
    qscore_kernel<<<Bsz * Uu, 64>>>(hs, query_w, key_b);
    topk_kernel<<<1, Bsz>>>();
    inp_kernel<<<(Bsz * Uu * IVP + 255) / 256, 256>>>(value_b);
    hsconv_kernel<<<(Bsz * Uu * Hh + 255) / 256, 256>>>(hs);

    // --- preact = inp@i2h + hs@h2h (dual pass, K=416+512) ---
    bgemm<<<dim3(2048 / 128, Bsz / 128, Uu), 256, SMEM_TOTAL>>>(
        p_inp_h, p_inp_l, IVP, Uu * IVP, w_i2h_h, w_i2h_l, IVP,
        p_hs_h,  p_hs_l,  Hh,  Uu * Hh,  w_h2h_h, w_h2h_l, Hh,
        2048, p_pre, 0, nullptr, nullptr, nullptr, nullptr, nullptr);

    gates_kernel<<<(Bsz * Uu * Hh + 255) / 256, 256>>>(cs, out_cs);

    // --- qc & kc merged (N=128 each, mode 2) ---
    bgemm<<<dim3(2, Bsz / 128, Uu), 256, SMEM_TOTAL>>>(
        p_hth, p_htl, Hh, Uu * Hh, w_qc_h, w_qc_l, Hh,
        nullptr, nullptr, 0, 0, w_kc_h, w_kc_l, 0,
        128, p_qc, 2, p_kc, nullptr, nullptr, nullptr, nullptr);

    // --- vc (N=2048) ---
    bgemm<<<dim3(2048 / 128, Bsz / 128, Uu), 256, SMEM_TOTAL>>>(
        p_hth, p_htl, Hh, Uu * Hh, w_vc_h, w_vc_l, Hh,
        nullptr, nullptr, 0, 0, nullptr, nullptr, 0,
        2048, p_vc, 0, nullptr, nullptr, nullptr, nullptr, nullptr);

    attn_kernel<<<Bsz * NCHh, 256>>>();

    // --- co GEMM with fused hs_new epilogue ---
    bgemm<<<dim3(512 / 128, Bsz / 128, Uu), 256, SMEM_TOTAL>>>(
        p_ctx_h, p_ctx_l, NCHh * CVv, Uu * NCHh * CVv, w_co_h, w_co_l, NCHh * CVv,
        nullptr, nullptr, 0, 0, nullptr, nullptr, 0,
        512, nullptr, 1, nullptr, p_ht, p_mask, hs, out_hs);
}

// round 12
// speedup vs baseline: 2.2423x; 1.0810x over previous
#include <cuda_runtime.h>
#include <cuda_bf16.h>
#include <math.h>
#include <stddef.h>
#include <stdint.h>

#define Bsz 256
#define Dd  512
#define Hh  512
#define Uu  24
#define Kk  8
#define IKk 64
#define IVv 400
#define IVP 416        // IVv padded to multiple of 32
#define CKk 32
#define NCHh 4
#define CVv 512

typedef __nv_bfloat16 bf16;

// ---------------- fp32 scratch ----------------
__device__ float g_k0[Bsz * IKk];
__device__ float g_v0[Bsz * IVv];
__device__ float g_s0[Bsz * Uu];
__device__ float g_p0[Bsz * Uu];
__device__ float g_mask[Bsz * Uu];
__device__ float g_pre[(size_t)Bsz * Uu * 4 * Hh];   // 50 MB
__device__ float g_ht[Bsz * Uu * Hh];
__device__ float g_qc[Bsz * Uu * NCHh * CKk];
__device__ float g_kc[Bsz * Uu * NCHh * CKk];
__device__ float g_vc[(size_t)Bsz * Uu * NCHh * CVv];  // 50 MB

// ---------------- bf16 hi/lo activations (A operands) -------------
__device__ __align__(16) bf16 g_inp_h[Bsz * Uu * IVP];
__device__ __align__(16) bf16 g_inp_l[Bsz * Uu * IVP];
__device__ __align__(16) bf16 g_hs_h[Bsz * Uu * Hh];
__device__ __align__(16) bf16 g_hs_l[Bsz * Uu * Hh];
__device__ __align__(16) bf16 g_hth[Bsz * Uu * Hh];
__device__ __align__(16) bf16 g_htl[Bsz * Uu * Hh];
__device__ __align__(16) bf16 g_ctx_h[(size_t)Bsz * Uu * NCHh * CVv];
__device__ __align__(16) bf16 g_ctx_l[(size_t)Bsz * Uu * NCHh * CVv];

// ---------------- bf16 hi/lo weights, NATIVE [u][Kp][N] layout ---------
#define I2H_SZ ((size_t)24 * IVP * 2048)
#define H2H_SZ ((size_t)24 * 512 * 2048)
#define QCW_SZ ((size_t)24 * 512 * 128)
#define VCW_SZ ((size_t)24 * 512 * 2048)
#define COW_SZ ((size_t)24 * 2048 * 512)
__device__ __align__(16) bf16 g_i2h_h[I2H_SZ]; __device__ __align__(16) bf16 g_i2h_l[I2H_SZ];
__device__ __align__(16) bf16 g_h2h_h[H2H_SZ]; __device__ __align__(16) bf16 g_h2h_l[H2H_SZ];
__device__ __align__(16) bf16 g_qcw_h[QCW_SZ]; __device__ __align__(16) bf16 g_qcw_l[QCW_SZ];
__device__ __align__(16) bf16 g_kcw_h[QCW_SZ]; __device__ __align__(16) bf16 g_kcw_l[QCW_SZ];
__device__ __align__(16) bf16 g_vcw_h[VCW_SZ]; __device__ __align__(16) bf16 g_vcw_l[VCW_SZ];
__device__ __align__(16) bf16 g_cow_h[COW_SZ]; __device__ __align__(16) bf16 g_cow_l[COW_SZ];

// ===================== PTX helpers (baseline sm_80+ only) =====================
__device__ __forceinline__ uint32_t smem_u32(const void* p) {
    uint32_t a;
    asm("{ .reg .u64 t; cvta.to.shared.u64 t, %1; cvt.u32.u64 %0, t; }" : "=r"(a) : "l"(p));
    return a;
}
__device__ __forceinline__ void cp16(uint32_t dst, const void* src) {
    asm volatile("cp.async.cg.shared.global [%0], [%1], 16;"
                 :: "r"(dst), "l"(__cvta_generic_to_global(src)) : "memory");
}
__device__ __forceinline__ void cp_commit() {
    asm volatile("cp.async.commit_group;" ::: "memory");
}
__device__ __forceinline__ void cp_wait0() {
    asm volatile("cp.async.wait_group 0;" ::: "memory");
}
__device__ __forceinline__ void cp_wait1() {
    asm volatile("cp.async.wait_group 1;" ::: "memory");
}
__device__ __forceinline__ void ldsm_x4(uint32_t* r, uint32_t addr) {
    asm volatile("ldmatrix.sync.aligned.m8n8.x4.shared.b16 {%0,%1,%2,%3}, [%4];"
                 : "=r"(r[0]), "=r"(r[1]), "=r"(r[2]), "=r"(r[3]) : "r"(addr));
}
__device__ __forceinline__ void ldsm_x2_trans(uint32_t* r, uint32_t addr) {
    asm volatile("ldmatrix.sync.aligned.m8n8.x2.trans.shared.b16 {%0,%1}, [%2];"
                 : "=r"(r[0]), "=r"(r[1]) : "r"(addr));
}
__device__ __forceinline__ void mma_bf16(float* d, const uint32_t* a, const uint32_t* b) {
    asm volatile(
        "mma.sync.aligned.m16n8k16.row.col.f32.bf16.bf16.f32 "
        "{%0,%1,%2,%3}, {%4,%5,%6,%7}, {%8,%9}, {%0,%1,%2,%3};"
        : "+f"(d[0]), "+f"(d[1]), "+f"(d[2]), "+f"(d[3])
        : "r"(a[0]), "r"(a[1]), "r"(a[2]), "r"(a[3]), "r"(b[0]), "r"(b[1]));
}

// ---------------- stage A: k0 = x@key_w+key_b, v0 = x@value_w+value_b ------
__global__ void kv_kernel(const float* __restrict__ x,
                          const float* __restrict__ key_w, const float* __restrict__ key_b,
                          const float* __restrict__ value_w, const float* __restrict__ value_b) {
    int b = blockIdx.x;
    __shared__ float xs[Dd];
    int tid = threadIdx.x; // 512
    xs[tid] = x[(size_t)b * Dd + tid];
    __syncthreads();
    if (tid < IVv) {
        float acc = value_b[tid];
        #pragma unroll 8
        for (int d = 0; d < Dd; d++) acc += xs[d] * value_w[(size_t)d * IVv + tid];
        g_v0[b * IVv + tid] = acc;
    } else if (tid < IVv + IKk) {
        int ik = tid - IVv;
        float acc = key_b[ik];
        #pragma unroll 8
        for (int d = 0; d < Dd; d++) acc += xs[d] * key_w[(size_t)d * IKk + ik];
        g_k0[b * IKk + ik] = acc;
    }
}

// ---------------- stage A: q, scores, probs ----------------
__global__ void qscore_kernel(const float* __restrict__ hs,
                              const float* __restrict__ query_w,
                              const float* __restrict__ key_b) {
    int bu = blockIdx.x;
    int b = bu / Uu, u = bu % Uu;
    int ik = threadIdx.x; // 64
    __shared__ float hss[Hh];
    for (int i = ik; i < Hh; i += 64) hss[i] = hs[(size_t)bu * Hh + i];
    __syncthreads();
    const float* qw = query_w + (size_t)u * Hh * IKk;
    float q = 0.f;
    #pragma unroll 8
    for (int d = 0; d < Hh; d++) q += hss[d] * qw[(size_t)d * IKk + ik];
    float p0 = q * g_k0[b * IKk + ik];
    float p1 = q * key_b[ik];
    #pragma unroll
    for (int off = 16; off > 0; off >>= 1) {
        p0 += __shfl_down_sync(0xffffffffu, p0, off);
        p1 += __shfl_down_sync(0xffffffffu, p1, off);
    }
    __shared__ float r0[2], r1[2];
    if ((ik & 31) == 0) { r0[ik >> 5] = p0; r1[ik >> 5] = p1; }
    __syncthreads();
    if (ik == 0) {
        float s0 = (r0[0] + r0[1]) * 0.125f;
        float s1 = (r1[0] + r1[1]) * 0.125f;
        g_s0[bu] = s0;
        float m = fmaxf(s0, s1);
        float e0 = expf(s0 - m), e1 = expf(s1 - m);
        g_p0[bu] = e0 / (e0 + e1);
    }
}

// ---------------- top-k mask ----------------
__global__ void topk_kernel() {
    int b = threadIdx.x;
    float s[Uu];
    #pragma unroll
    for (int u = 0; u < Uu; u++) s[u] = g_s0[b * Uu + u];
    #pragma unroll
    for (int u = 0; u < Uu; u++) {
        int cnt = 0;
        #pragma unroll
        for (int t = 0; t < Uu; t++)
            if (s[t] > s[u] || (s[t] == s[u] && t < u)) cnt++;
        g_mask[b * Uu + u] = (cnt < Kk) ? 1.f : 0.f;
    }
}

// ---------------- inp (bf16 hi/lo out, padded K to 416) ----------------
__global__ void inp_kernel(const float* __restrict__ value_b) {
    int idx = blockIdx.x * blockDim.x + threadIdx.x;
    if (idx >= Bsz * Uu * IVP) return;
    int iv = idx % IVP;
    int bu = idx / IVP;
    int b = bu / Uu;
    float v = 0.f;
    if (iv < IVv) {
        float p0 = g_p0[bu];
        v = p0 * g_v0[b * IVv + iv] + (1.f - p0) * value_b[iv];
        v *= g_mask[bu];
    }
    bf16 h = __float2bfloat16_rn(v);
    g_inp_h[idx] = h;
    g_inp_l[idx] = __float2bfloat16_rn(v - __bfloat162float(h));
}

// ---------------- hs -> bf16 hi/lo ----------------
__global__ void hsconv_kernel(const float* __restrict__ hs) {
    int idx = blockIdx.x * blockDim.x + threadIdx.x;
    if (idx >= Bsz * Uu * Hh) return;
    float v = hs[idx];
    bf16 h = __float2bfloat16_rn(v);
    g_hs_h[idx] = h;
    g_hs_l[idx] = __float2bfloat16_rn(v - __bfloat162float(h));
}

// ---------------- streaming weight split: W[u][K][N] f32 -> hi/lo bf16 -------
// Same layout, K zero-padded to Kp. float4 reads, packed 8B writes per array.
__global__ void wsplit_kernel(const float* __restrict__ W, bf16* __restrict__ Wh,
                              bf16* __restrict__ Wl, int K, int Kp, int N) {
    int u = blockIdx.z;
    size_t i4 = ((size_t)blockIdx.x * blockDim.x + threadIdx.x) * 4;
    if (i4 >= (size_t)Kp * N) return;
    int k = (int)(i4 / N);
    int n = (int)(i4 % N);
    float4 v;
    if (k < K) v = *(const float4*)(W + (size_t)u * K * N + (size_t)k * N + n);
    else       v = make_float4(0.f, 0.f, 0.f, 0.f);
    bf16 h0 = __float2bfloat16_rn(v.x), h1 = __float2bfloat16_rn(v.y);
    bf16 h2 = __float2bfloat16_rn(v.z), h3 = __float2bfloat16_rn(v.w);
    bf16 l0 = __float2bfloat16_rn(v.x - __bfloat162float(h0));
    bf16 l1 = __float2bfloat16_rn(v.y - __bfloat162float(h1));
    bf16 l2 = __float2bfloat16_rn(v.z - __bfloat162float(h2));
    bf16 l3 = __float2bfloat16_rn(v.w - __bfloat162float(h3));
    uint2 ph, pl;
    ph.x = (uint32_t)__bfloat16_as_ushort(h0) | ((uint32_t)__bfloat16_as_ushort(h1) << 16);
    ph.y = (uint32_t)__bfloat16_as_ushort(h2) | ((uint32_t)__bfloat16_as_ushort(h3) << 16);
    pl.x = (uint32_t)__bfloat16_as_ushort(l0) | ((uint32_t)__bfloat16_as_ushort(l1) << 16);
    pl.y = (uint32_t)__bfloat16_as_ushort(l2) | ((uint32_t)__bfloat16_as_ushort(l3) << 16);
    size_t o = (size_t)u * Kp * N + i4;
    *(uint2*)(Wh + o) = ph;
    *(uint2*)(Wl + o) = pl;
}

// ===================== bf16-split tensor-core GEMM (mma.sync) =====================
// D[(b*U+u)*ldc + n] = sum_k A(b,u,k) * W[u][k][n], hi/lo split, fp32 acc.
// CTA tile 128x128, 8 warps (2 M x 4 N), warp tile 64x32, BK=32, cp.async 2-stage.
// B tiles loaded from NATIVE row-major [k][n]; fragments via ldmatrix.trans.
// mode 0: store C. mode 1: out = mask ? acc+ht : hs_in. mode 2: blockIdx.x picks
//         (Bh1,C) vs (Bh2,C2), n0=0, single pass.
#define BKc   32
#define BKp   40
#define BNp   136
#define AST   (128 * BKp * 2)     // 10240 B per A tile
#define BST   (BKc * BNp * 2)     // 8704 B per B tile
#define STAGE (2 * AST + 2 * BST) // 37888 B
#define SMEMT (2 * STAGE)         // 75776 B

extern __shared__ char gsm[];

struct GArgs {
    const bf16 *Auh, *Aul, *Buh, *Bul;  // B bases already offset by n0
    int K, ars, ldw;
};

__device__ __forceinline__ void issue_loads(const GArgs& ga, uint32_t sbuf,
                                            int k0, int tid) {
    #pragma unroll
    for (int h = 0; h < 2; h++) {
        int c = tid + h * 256;
        // A: 512 chunks/array: row = c>>2 (0..127), seg = c&3
        int arow = c >> 2, aseg = c & 3;
        uint32_t ad = sbuf + (uint32_t)(arow * (BKp * 2) + aseg * 16);
        const bf16* a_h = ga.Auh + (size_t)arow * ga.ars + k0 + aseg * 8;
        const bf16* a_l = ga.Aul + (size_t)arow * ga.ars + k0 + aseg * 8;
        cp16(ad,       a_h);
        cp16(ad + AST, a_l);
        // B: 512 chunks/array: row = c>>4 (0..31), nseg = c&15
        int brow = c >> 4, bseg = c & 15;
        uint32_t bd = sbuf + 2 * AST + (uint32_t)(brow * (BNp * 2) + bseg * 16);
        const bf16* b_h = ga.Buh + (size_t)(k0 + brow) * ga.ldw + bseg * 8;
        const bf16* b_l = ga.Bul + (size_t)(k0 + brow) * ga.ldw + bseg * 8;
        cp16(bd,       b_h);
        cp16(bd + BST, b_l);
    }
    cp_commit();
}

__global__ void __launch_bounds__(256) bgemm(
    const bf16* __restrict__ Ah1, const bf16* __restrict__ Al1, int a1_uoff, int a1_rs,
    const bf16* __restrict__ Bh1, const bf16* __restrict__ Bl1, int K1,
    const bf16* __restrict__ Ah2, const bf16* __restrict__ Al2, int a2_uoff, int a2_rs,
    const bf16* __restrict__ Bh2, const bf16* __restrict__ Bl2, int K2,
    int ldc, float* __restrict__ C, int mode, float* __restrict__ C2,
    const float* __restrict__ ht, const float* __restrict__ mk,
    const float* __restrict__ hs_in, float* __restrict__ outp)
{
    uint32_t sb = smem_u32(gsm);
    int tid  = threadIdx.x;
    int lane = tid & 31, wid = tid >> 5;
    int wm = wid & 1, wn = wid >> 1;
    int u = blockIdx.z, m0 = blockIdx.y * 128;
    int n0;
    const bf16 *Bh = Bh1, *Bl = Bl1;
    float* Csel = C;
    if (mode == 2) {
        n0 = 0;
        if (blockIdx.x) { Bh = Bh2; Bl = Bl2; Csel = C2; }
    } else {
        n0 = blockIdx.x * 128;
    }

    float acc[4][4][4];
    #pragma unroll
    for (int i = 0; i < 4; i++)
        #pragma unroll
        for (int j = 0; j < 4; j++)
            #pragma unroll
            for (int k = 0; k < 4; k++) acc[i][j][k] = 0.f;

    // lane-dependent ldmatrix offsets
    int a_ro = lane & 15, a_cg = lane >> 4;
    int b_kr = (lane & 7) + 8 * ((lane >> 3) & 1);  // k-row within 16-k step

    int npass = (mode != 2 && K2 > 0) ? 2 : 1;
    #pragma unroll 1
    for (int pass = 0; pass < npass; pass++) {
        GArgs ga;
        if (pass == 0) {
            ga.Auh = Ah1 + (size_t)u * a1_uoff + (size_t)m0 * a1_rs;
            ga.Aul = Al1 + (size_t)u * a1_uoff + (size_t)m0 * a1_rs;
            ga.Buh = Bh + (size_t)u * K1 * ldc + n0;
            ga.Bul = Bl + (size_t)u * K1 * ldc + n0;
            ga.K = K1; ga.ars = a1_rs; ga.ldw = ldc;
        } else {
            ga.Auh = Ah2 + (size_t)u * a2_uoff + (size_t)m0 * a2_rs;
            ga.Aul = Al2 + (size_t)u * a2_uoff + (size_t)m0 * a2_rs;
            ga.Buh = Bh2 + (size_t)u * K2 * ldc + n0;
            ga.Bul = Bl2 + (size_t)u * K2 * ldc + n0;
            ga.K = K2; ga.ars = a2_rs; ga.ldw = ldc;
        }
        int T = ga.K / BKc;

        issue_loads(ga, sb, 0, tid);

        #pragma unroll 1
        for (int t = 0; t < T; t++) {
            uint32_t scur = sb + (uint32_t)((t & 1) * STAGE);
            if (t + 1 < T) {
                issue_loads(ga, sb + (uint32_t)(((t + 1) & 1) * STAGE), (t + 1) * BKc, tid);
                cp_wait1();
            } else {
                cp_wait0();
            }
            __syncthreads();

            #pragma unroll
            for (int ks = 0; ks < 2; ks++) {
                int koff = ks * 16;
                uint32_t a_h[4][4], a_l[4][4], b_h[4][2], b_l[4][2];
                #pragma unroll
                for (int mt = 0; mt < 4; mt++) {
                    uint32_t ad = scur +
                        (uint32_t)(((wm * 64 + mt * 16 + a_ro) * BKp + koff + a_cg * 8) * 2);
                    ldsm_x4(a_h[mt], ad);
                    ldsm_x4(a_l[mt], ad + AST);
                }
                #pragma unroll
                for (int nt = 0; nt < 4; nt++) {
                    uint32_t bd = scur + 2 * AST +
                        (uint32_t)(((koff + b_kr) * BNp + wn * 32 + nt * 8) * 2);
                    ldsm_x2_trans(b_h[nt], bd);
                    ldsm_x2_trans(b_l[nt], bd + BST);
                }
                // split-major ordering: consecutive MMAs hit independent accumulators
                #pragma unroll
                for (int mt = 0; mt < 4; mt++)
                    #pragma unroll
                    for (int nt = 0; nt < 4; nt++)
                        mma_bf16(acc[mt][nt], a_h[mt], b_h[nt]);
                #pragma unroll
                for (int mt = 0; mt < 4; mt++)
                    #pragma unroll
                    for (int nt = 0; nt < 4; nt++)
                        mma_bf16(acc[mt][nt], a_h[mt], b_l[nt]);
                #pragma unroll
                for (int mt = 0; mt < 4; mt++)
                    #pragma unroll
                    for (int nt = 0; nt < 4; nt++)
                        mma_bf16(acc[mt][nt], a_l[mt], b_h[nt]);
            }
            __syncthreads();
        }
    }

    // epilogue: D fragment m16n8 -> rows lane>>2 (+8), cols (lane&3)*2
    #pragma unroll
    for (int mt = 0; mt < 4; mt++) {
        #pragma unroll
        for (int half = 0; half < 2; half++) {
            int row = m0 + wm * 64 + mt * 16 + (lane >> 2) + 8 * half;
            int bu = row * Uu + u;
            bool sel = (mode == 1) ? (mk[bu] != 0.f) : false;
            #pragma unroll
            for (int nt = 0; nt < 4; nt++) {
                int col = n0 + wn * 32 + nt * 8 + (lane & 3) * 2;
                size_t idx = (size_t)bu * ldc + col;
                float2 v;
                v.x = acc[mt][nt][2 * half + 0];
                v.y = acc[mt][nt][2 * half + 1];
                if (mode == 1) {
                    if (sel) {
                        float2 h = *(const float2*)&ht[idx];
                        v.x += h.x; v.y += h.y;
                    } else {
                        v = *(const float2*)&hs_in[idx];
                    }
                    *(float2*)&outp[idx] = v;
                } else {
                    *(float2*)&Csel[idx] = v;
                }
            }
        }
    }
}

// ---------------- LSTM gates + cs_new + ht (f32 + bf16 hi/lo) ----------------
__global__ void gates_kernel(const float* __restrict__ cs, float* __restrict__ out_cs) {
    int idx = blockIdx.x * blockDim.x + threadIdx.x;
    if (idx >= Bsz * Uu * Hh) return;
    int h  = idx % Hh;
    int bu = idx / Hh;
    size_t base = (size_t)bu * 4 * Hh;
    float pi = g_pre[base + h];
    float pf = g_pre[base + Hh + h];
    float po = g_pre[base + 2 * Hh + h];
    float pg = g_pre[base + 3 * Hh + h];
    float it = 1.f / (1.f + expf(-pi));
    float ft = 1.f / (1.f + expf(-pf));
    float ot = 1.f / (1.f + expf(-po));
    float gt = tanhf(pg);
    float c  = cs[idx] * ft + it * gt;
    float htv = ot * tanhf(c);
    g_ht[idx] = htv;
    bf16 hh = __float2bfloat16_rn(htv);
    g_hth[idx] = hh;
    g_htl[idx] = __float2bfloat16_rn(htv - __bfloat162float(hh));
    out_cs[idx] = (g_mask[bu] != 0.f) ? c : cs[idx];
}

// ---------------- communication attention: ctx (bf16 hi/lo out) --------------
__global__ void __launch_bounds__(256) attn_kernel() {
    int b = blockIdx.x >> 2;
    int head = blockIdx.x & 3;
    __shared__ float qcs[Uu][CKk + 1], kcs[Uu][CKk + 1], att[Uu][Uu];
    int tid = threadIdx.x;
    for (int i = tid; i < Uu * CKk; i += 256) {
        int uu = i / CKk, c = i % CKk;
        size_t base = (size_t)(b * Uu + uu) * (NCHh * CKk) + head * CKk + c;
        qcs[uu][c] = g_qc[base];
        kcs[uu][c] = g_kc[base];
    }
    __syncthreads();
    for (int i = tid; i < Uu * Uu; i += 256) {
        int uu = i / Uu, t = i % Uu;
        float s = 0.f;
        #pragma unroll
        for (int c = 0; c < CKk; c++) s += qcs[uu][c] * kcs[t][c];
        att[uu][t] = s * 0.17677669529663687f;
    }
    __syncthreads();
    if (tid < Uu) {
        float m = -1e30f;
        #pragma unroll
        for (int t = 0; t < Uu; t++) m = fmaxf(m, att[tid][t]);
        float sum = 0.f;
        #pragma unroll
        for (int t = 0; t < Uu; t++) {
            float e = expf(att[tid][t] - m);
            att[tid][t] = e;
            sum += e;
        }
        float inv = 1.f / sum;
        #pragma unroll
        for (int t = 0; t < Uu; t++) att[tid][t] *= inv;
    }
    __syncthreads();
    float accx[Uu], accy[Uu];
    #pragma unroll
    for (int uu = 0; uu < Uu; uu++) { accx[uu] = 0.f; accy[uu] = 0.f; }
    int v0 = tid * 2;
    #pragma unroll 4
    for (int t = 0; t < Uu; t++) {
        float2 vv = *(const float2*)&g_vc[(size_t)(b * Uu + t) * (NCHh * CVv) + head * CVv + v0];
        #pragma unroll
        for (int uu = 0; uu < Uu; uu++) {
            float a = att[uu][t];
            accx[uu] += a * vv.x;
            accy[uu] += a * vv.y;
        }
    }
    #pragma unroll
    for (int uu = 0; uu < Uu; uu++) {
        size_t o = (size_t)(b * Uu + uu) * (NCHh * CVv) + head * CVv + v0;
        bf16 hx = __float2bfloat16_rn(accx[uu]);
        bf16 hy = __float2bfloat16_rn(accy[uu]);
        g_ctx_h[o]     = hx;
        g_ctx_h[o + 1] = hy;
        g_ctx_l[o]     = __float2bfloat16_rn(accx[uu] - __bfloat162float(hx));
        g_ctx_l[o + 1] = __float2bfloat16_rn(accy[uu] - __bfloat162float(hy));
    }
}

// ---------------- launch ----------------
extern "C" void kernel_launch(void* const* d_in, const int* in_sizes, int n_in,
                              void* d_out, int out_size) {
    const float* x       = (const float*)d_in[0];
    const float* hs      = (const float*)d_in[1];
    const float* cs      = (const float*)d_in[2];
    const float* key_w   = (const float*)d_in[3];
    const float* key_b   = (const float*)d_in[4];
    const float* value_w = (const float*)d_in[5];
    const float* value_b = (const float*)d_in[6];
    const float* query_w = (const float*)d_in[7];
    const float* i2h_w   = (const float*)d_in[8];
    const float* h2h_w   = (const float*)d_in[9];
    const float* qc_w    = (const float*)d_in[10];
    const float* kc_w    = (const float*)d_in[11];
    const float* vc_w    = (const float*)d_in[12];
    const float* co_w    = (const float*)d_in[13];
    float* out    = (float*)d_out;
    float* out_hs = out;
    float* out_cs = out + (size_t)Bsz * Uu * Hh;

    cudaFuncSetAttribute(bgemm, cudaFuncAttributeMaxDynamicSharedMemorySize, SMEMT);

    float *p_pre, *p_ht, *p_qc, *p_kc, *p_vc, *p_mask;
    cudaGetSymbolAddress((void**)&p_pre,  g_pre);
    cudaGetSymbolAddress((void**)&p_ht,   g_ht);
    cudaGetSymbolAddress((void**)&p_qc,   g_qc);
    cudaGetSymbolAddress((void**)&p_kc,   g_kc);
    cudaGetSymbolAddress((void**)&p_vc,   g_vc);
    cudaGetSymbolAddress((void**)&p_mask, g_mask);
    bf16 *p_inp_h, *p_inp_l, *p_hs_h, *p_hs_l, *p_hth, *p_htl, *p_ctx_h, *p_ctx_l;
    cudaGetSymbolAddress((void**)&p_inp_h, g_inp_h);
    cudaGetSymbolAddress((void**)&p_inp_l, g_inp_l);
    cudaGetSymbolAddress((void**)&p_hs_h,  g_hs_h);
    cudaGetSymbolAddress((void**)&p_hs_l,  g_hs_l);
    cudaGetSymbolAddress((void**)&p_hth,   g_hth);
    cudaGetSymbolAddress((void**)&p_htl,   g_htl);
    cudaGetSymbolAddress((void**)&p_ctx_h, g_ctx_h);
    cudaGetSymbolAddress((void**)&p_ctx_l, g_ctx_l);
    bf16 *w_i2h_h, *w_i2h_l, *w_h2h_h, *w_h2h_l, *w_qc_h, *w_qc_l,
         *w_kc_h, *w_kc_l, *w_vc_h, *w_vc_l, *w_co_h, *w_co_l;
    cudaGetSymbolAddress((void**)&w_i2h_h, g_i2h_h);
    cudaGetSymbolAddress((void**)&w_i2h_l, g_i2h_l);
    cudaGetSymbolAddress((void**)&w_h2h_h, g_h2h_h);
    cudaGetSymbolAddress((void**)&w_h2h_l, g_h2h_l);
    cudaGetSymbolAddress((void**)&w_qc_h,  g_qcw_h);
    cudaGetSymbolAddress((void**)&w_qc_l,  g_qcw_l);
    cudaGetSymbolAddress((void**)&w_kc_h,  g_kcw_h);
    cudaGetSymbolAddress((void**)&w_kc_l,  g_kcw_l);
    cudaGetSymbolAddress((void**)&w_vc_h,  g_vcw_h);
    cudaGetSymbolAddress((void**)&w_vc_l,  g_vcw_l);
    cudaGetSymbolAddress((void**)&w_co_h,  g_cow_h);
    cudaGetSymbolAddress((void**)&w_co_l,  g_cow_l);

    // --- streaming weight split (native layout, K padded) ---
    {
        auto blocks = [](int Kp, int N) { return (Kp * N / 4 + 255) / 256; };
        wsplit_kernel<<<dim3(blocks(IVP, 2048), 1, Uu), 256>>>(i2h_w, w_i2h_h, w_i2h_l, IVv, IVP, 2048);
        wsplit_kernel<<<dim3(blocks(512, 2048), 1, Uu), 256>>>(h2h_w, w_h2h_h, w_h2h_l, 512, 512, 2048);
        wsplit_kernel<<<dim3(blocks(512, 128),  1, Uu), 256>>>(qc_w,  w_qc_h,  w_qc_l,  512, 512, 128);
        wsplit_kernel<<<dim3(blocks(512, 128),  1, Uu), 256>>>(kc_w,  w_kc_h,  w_kc_l,  512, 512, 128);
        wsplit_kernel<<<dim3(blocks(512, 2048), 1, Uu), 256>>>(vc_w,  w_vc_h,  w_vc_l,  512, 512, 2048);
        wsplit_kernel<<<dim3(blocks(2048, 512), 1, Uu), 256>>>(co_w,  w_co_h,  w_co_l,  2048, 2048, 512);
    }

    // --- stage A ---
    kv_kernel<<<Bsz, 512>>>(x, key_w, key_b, value_w, value_b);
    qscore_kernel<<<Bsz * Uu, 64>>>(hs, query_w, key_b);
    topk_kernel<<<1, Bsz>>>();
    inp_kernel<<<(Bsz * Uu * IVP + 255) / 256, 256>>>(value_b);
    hsconv_kernel<<<(Bsz * Uu * Hh + 255) / 256, 256>>>(hs);

    // --- preact = inp@i2h + hs@h2h (dual pass, K=416+512) ---
    bgemm<<<dim3(2048 / 128, Bsz / 128, Uu), 256, SMEMT>>>(
        p_inp_h, p_inp_l, IVP, Uu * IVP, w_i2h_h, w_i2h_l, IVP,
        p_hs_h,  p_hs_l,  Hh,  Uu * Hh,  w_h2h_h, w_h2h_l, Hh,
        2048, p_pre, 0, nullptr, nullptr, nullptr, nullptr, nullptr);

    gates_kernel<<<(Bsz * Uu * Hh + 255) / 256, 256>>>(cs, out_cs);

    // --- qc & kc merged (N=128 each, mode 2) ---
    bgemm<<<dim3(2, Bsz / 128, Uu), 256, SMEMT>>>(
        p_hth, p_htl, Hh, Uu * Hh, w_qc_h, w_qc_l, Hh,
        nullptr, nullptr, 0, 0, w_kc_h, w_kc_l, 0,
        128, p_qc, 2, p_kc, nullptr, nullptr, nullptr, nullptr);

    // --- vc (N=2048) ---
    bgemm<<<dim3(2048 / 128, Bsz / 128, Uu), 256, SMEMT>>>(
        p_hth, p_htl, Hh, Uu * Hh, w_vc_h, w_vc_l, Hh,
        nullptr, nullptr, 0, 0, nullptr, nullptr, 0,
        2048, p_vc, 0, nullptr, nullptr, nullptr, nullptr, nullptr);

    attn_kernel<<<Bsz * NCHh, 256>>>();

    // --- co GEMM with fused hs_new epilogue ---
    bgemm<<<dim3(512 / 128, Bsz / 128, Uu), 256, SMEMT>>>(
        p_ctx_h, p_ctx_l, NCHh * CVv, Uu * NCHh * CVv, w_co_h, w_co_l, NCHh * CVv,
        nullptr, nullptr, 0, 0, nullptr, nullptr, 0,
        512, nullptr, 1, nullptr, p_ht, p_mask, hs, out_hs);
}